// round 1
// baseline (speedup 1.0000x reference)
#include <cuda_runtime.h>

#define B_TOTAL 4096
#define V_TOTAL 1024
#define DD 64
#define TB 64
#define TV 64
#define LDX 66   // padded row stride (words) for xs: rows 8 apart land 16 banks apart

__device__ unsigned int g_rowmin[B_TOTAL];
__device__ unsigned int g_colmin[V_TOTAL];

__global__ void init_mins() {
    int i = blockIdx.x * blockDim.x + threadIdx.x;
    if (i < B_TOTAL) g_rowmin[i] = 0x7F800000u;  // +inf bit pattern
    if (i < V_TOTAL) g_colmin[i] = 0x7F800000u;
}

__device__ __forceinline__ unsigned long long addf32x2(unsigned long long a,
                                                      unsigned long long b) {
    unsigned long long r;
    asm("add.rn.f32x2 %0, %1, %2;" : "=l"(r) : "l"(a), "l"(b));
    return r;
}

__global__ __launch_bounds__(128)
void dist_kernel(const float* __restrict__ x, const float* __restrict__ p,
                 float* __restrict__ out) {
    __shared__ float xs[TB][LDX];          // b-major, k contiguous (k-pairs 8B aligned)
    __shared__ float ps2[DD / 2][TV][2];   // k-pair interleaved: [kk][v][{k,k+1}], negated
    __shared__ unsigned int col_s[TV];

    const int tid = threadIdx.x;
    const int b0 = blockIdx.y * TB;
    const int v0 = blockIdx.x * TV;

    // ---- load x tile (64x64 floats) ----
    for (int i = tid; i < TB * (DD / 4); i += 128) {
        int r = i >> 4;
        int c = (i & 15) << 2;
        float4 v = *(const float4*)(x + (size_t)(b0 + r) * DD + c);
        xs[r][c]     = v.x;
        xs[r][c + 1] = v.y;
        xs[r][c + 2] = v.z;
        xs[r][c + 3] = v.w;
    }
    // ---- load p tile negated into k-pair-interleaved layout ----
    for (int i = tid; i < TV * (DD / 4); i += 128) {
        int r = i >> 4;
        int c = (i & 15) << 2;
        float4 v = *(const float4*)(p + (size_t)(v0 + r) * DD + c);
        int kk = c >> 1;
        ps2[kk][r][0]     = -v.x;
        ps2[kk][r][1]     = -v.y;
        ps2[kk + 1][r][0] = -v.z;
        ps2[kk + 1][r][1] = -v.w;
    }
    if (tid < TV) col_s[tid] = 0x7F800000u;
    __syncthreads();

    const int tx = tid & 15;   // v direction: v = tx + 16*j  (strided -> bank-conflict-free)
    const int ty = tid >> 4;   // 0..7, b direction: b = ty*8 + i
    const int brow = ty * 8;

    unsigned long long acc[8][4];
#pragma unroll
    for (int i = 0; i < 8; i++)
#pragma unroll
        for (int j = 0; j < 4; j++) acc[i][j] = 0ull;

#pragma unroll 2
    for (int kk = 0; kk < DD / 2; kk++) {
        unsigned long long xr[8], pr[4];
#pragma unroll
        for (int i = 0; i < 8; i++)
            xr[i] = *(const unsigned long long*)&xs[brow + i][kk * 2];
#pragma unroll
        for (int j = 0; j < 4; j++)
            pr[j] = *(const unsigned long long*)&ps2[kk][tx + 16 * j][0];
#pragma unroll
        for (int i = 0; i < 8; i++) {
#pragma unroll
            for (int j = 0; j < 4; j++) {
                unsigned long long d = addf32x2(xr[i], pr[j]);   // x - p (p pre-negated)
                d &= 0x7FFFFFFF7FFFFFFFull;                      // packed |.| (2x LOP3, ALU pipe)
                acc[i][j] = addf32x2(acc[i][j], d);
            }
        }
    }

    // ---- horizontal sum of packed pairs ----
    float dist[8][4];
#pragma unroll
    for (int i = 0; i < 8; i++)
#pragma unroll
        for (int j = 0; j < 4; j++) {
            unsigned long long a = acc[i][j];
            float lo = __uint_as_float((unsigned int)(a & 0xFFFFFFFFull));
            float hi = __uint_as_float((unsigned int)(a >> 32));
            dist[i][j] = lo + hi;
        }

    // ---- write distances (coalesced: lanes tx cover 16 consecutive v per j) ----
#pragma unroll
    for (int i = 0; i < 8; i++) {
        size_t rowbase = (size_t)(b0 + brow + i) * V_TOTAL + v0;
#pragma unroll
        for (int j = 0; j < 4; j++)
            out[rowbase + tx + 16 * j] = dist[i][j];
    }

    // ---- row mins (min over v): local min over j, butterfly over the 16 tx lanes ----
#pragma unroll
    for (int i = 0; i < 8; i++) {
        float rm = fminf(fminf(dist[i][0], dist[i][1]), fminf(dist[i][2], dist[i][3]));
        rm = fminf(rm, __shfl_xor_sync(0xFFFFFFFFu, rm, 1));
        rm = fminf(rm, __shfl_xor_sync(0xFFFFFFFFu, rm, 2));
        rm = fminf(rm, __shfl_xor_sync(0xFFFFFFFFu, rm, 4));
        rm = fminf(rm, __shfl_xor_sync(0xFFFFFFFFu, rm, 8));
        if (tx == 0)
            atomicMin(&g_rowmin[b0 + brow + i], __float_as_uint(rm));
    }

    // ---- col mins (min over b): local min over i, smem atomic across ty/warps ----
#pragma unroll
    for (int j = 0; j < 4; j++) {
        float cm = dist[0][j];
#pragma unroll
        for (int i = 1; i < 8; i++) cm = fminf(cm, dist[i][j]);
        atomicMin(&col_s[tx + 16 * j], __float_as_uint(cm));
    }
    __syncthreads();
    if (tid < TV)
        atomicMin(&g_colmin[v0 + tid], col_s[tid]);
}

__global__ void finalize(float* __restrict__ out) {
    __shared__ float sd[1024];
    int t = threadIdx.x;

    // r1_cost = mean over v of (min over b) = mean(colmin)
    sd[t] = __uint_as_float(g_colmin[t]);
    __syncthreads();
    for (int s = 512; s > 0; s >>= 1) {
        if (t < s) sd[t] += sd[t + s];
        __syncthreads();
    }
    if (t == 0)
        out[(size_t)B_TOTAL * V_TOTAL] = sd[0] / (float)V_TOTAL;
    __syncthreads();

    // r2_cost = mean over b of (min over v) = mean(rowmin)
    float rs = 0.f;
    for (int i = t; i < B_TOTAL; i += 1024)
        rs += __uint_as_float(g_rowmin[i]);
    sd[t] = rs;
    __syncthreads();
    for (int s = 512; s > 0; s >>= 1) {
        if (t < s) sd[t] += sd[t + s];
        __syncthreads();
    }
    if (t == 0)
        out[(size_t)B_TOTAL * V_TOTAL + 1] = sd[0] / (float)B_TOTAL;
}

extern "C" void kernel_launch(void* const* d_in, const int* in_sizes, int n_in,
                              void* d_out, int out_size) {
    (void)in_sizes; (void)n_in; (void)out_size;
    const float* x = (const float*)d_in[0];
    const float* p = (const float*)d_in[1];
    float* out = (float*)d_out;

    init_mins<<<16, 256>>>();
    dim3 grid(V_TOTAL / TV, B_TOTAL / TB);   // (16, 64) = 1024 blocks
    dist_kernel<<<grid, 128>>>(x, p, out);
    finalize<<<1, 1024>>>(out);
}